// round 3
// baseline (speedup 1.0000x reference)
#include <cuda_runtime.h>
#include <math.h>
#include <stdint.h>

// ---------------------------------------------------------------------------
// AutopoieticEngine: gather -> 2x(2-layer MLP) -> GRU -> faction sync/debate
//                    -> softmax-combine -> scatter
// Shapes (fixed by dataset): n_cells=262144, n_alive=131072, in_d=64, hid=128,
// out_d=64. Outputs flattened: combined(64) | mean_tension(1) | new_hiddens(262144*128)
// ---------------------------------------------------------------------------

#define HID    128
#define IN_D   64
#define OUT_D  64
#define CK     192      // in_d + hid
#define G3     384      // 3*hid
#define MEMW   65       // out_d + 1 (tension)
#define TILE_M 16
#define THREADS_B 128
#define N_ALIVE_MAX 131072
#define NCTA_MAX (N_ALIVE_MAX / TILE_M)

// -------------------- device-global scratch (no allocs allowed) ------------
__device__ float g_Wa1hT[HID * HID];        // [k][j] = Wa1[j][64+k]
__device__ float g_Wg1hT[HID * HID];
__device__ float g_Wa2T [HID * OUT_D];      // [k][j] = Wa2[j][k]
__device__ float g_Wg2T [HID * OUT_D];
__device__ float g_WihT [MEMW * G3];        // [k][j] = W_ih[j][k]
__device__ float g_WhhT [HID * G3];         // [k][j] = W_hh[j][k]
__device__ float g_xa1  [HID];              // ba1 + Wa1[:, :64] @ x
__device__ float g_xg1  [HID];
__device__ float g_bout [OUT_D];            // ba2 - bg2

__device__ float g_hpre [N_ALIVE_MAX * HID];   // pre-faction new_h (64 MB)
__device__ float g_partial_fm[NCTA_MAX * HID]; // per-CTA column sums of new_h
__device__ float g_partial_sm[NCTA_MAX * 66];  // per-CTA: 64 exp-weighted out cols, sum(e), sum(t)
__device__ float g_fm[8 * HID];                // faction means
__device__ float g_go[HID];                    // global mean

// ---------------------------------------------------------------------------
// Stage 2: weight transposes + x/bias folding (runs once per launch; tiny)
// ---------------------------------------------------------------------------
__global__ void setup_kernel(
    const float* __restrict__ x,
    const float* __restrict__ Wa1, const float* __restrict__ ba1,
    const float* __restrict__ Wa2, const float* __restrict__ ba2,
    const float* __restrict__ Wg1, const float* __restrict__ bg1,
    const float* __restrict__ Wg2, const float* __restrict__ bg2,
    const float* __restrict__ Wih, const float* __restrict__ Whh)
{
    int idx = blockIdx.x * blockDim.x + threadIdx.x;
    int stride = gridDim.x * blockDim.x;
    for (int i = idx; i < HID * HID; i += stride) {
        int k = i / HID, j = i % HID;
        g_Wa1hT[i] = Wa1[j * CK + IN_D + k];
        g_Wg1hT[i] = Wg1[j * CK + IN_D + k];
    }
    for (int i = idx; i < HID * OUT_D; i += stride) {
        int k = i / OUT_D, j = i % OUT_D;
        g_Wa2T[i] = Wa2[j * HID + k];
        g_Wg2T[i] = Wg2[j * HID + k];
    }
    for (int i = idx; i < MEMW * G3; i += stride) {
        int k = i / G3, j = i % G3;
        g_WihT[i] = Wih[j * MEMW + k];
    }
    for (int i = idx; i < HID * G3; i += stride) {
        int k = i / G3, j = i % G3;
        g_WhhT[i] = Whh[j * HID + k];
    }
    for (int j = idx; j < HID; j += stride) {
        float sa = ba1[j], sg = bg1[j];
        #pragma unroll 8
        for (int k = 0; k < IN_D; k++) {
            sa += x[k] * Wa1[j * CK + k];
            sg += x[k] * Wg1[j * CK + k];
        }
        g_xa1[j] = sa;
        g_xg1[j] = sg;
    }
    for (int j = idx; j < OUT_D; j += stride) g_bout[j] = ba2[j] - bg2[j];
}

// ---------------------------------------------------------------------------
// Stage 3: main fused kernel — 16 rows per CTA, 128 threads (column ownership)
// ---------------------------------------------------------------------------
__global__ void __launch_bounds__(THREADS_B)
main_kernel(const float* __restrict__ hiddens,
            const int*   __restrict__ alive_idx,
            const float* __restrict__ b_ih,
            const float* __restrict__ b_hh,
            int n)
{
    __shared__ float s_h  [TILE_M][HID];
    __shared__ float s_buf[TILE_M][HID];       // a1 then g1 (relu'd)
    __shared__ float s_out[TILE_M][OUT_D + 4]; // padded row (68 floats, 16B-aligned)
    __shared__ float s_t[TILE_M], s_e[TILE_M];
    __shared__ int   s_idx[TILE_M];

    const int t = threadIdx.x;
    const int base = blockIdx.x * TILE_M;

    if (t < TILE_M) s_idx[t] = alive_idx[base + t];
    __syncthreads();

    // ---- gather h tile (coalesced float4) ----
    for (int i = t; i < TILE_M * (HID / 4); i += THREADS_B) {
        int m = i >> 5, q = i & 31;
        ((float4*)s_h[m])[q] =
            ((const float4*)hiddens)[(size_t)s_idx[m] * (HID / 4) + q];
    }
    __syncthreads();

    // ---- a1 = relu(h @ Wa1h.T + xa1) ----
    {
        float acc[TILE_M];
        float bias = g_xa1[t];
        #pragma unroll
        for (int m = 0; m < TILE_M; m++) acc[m] = bias;
        #pragma unroll 4
        for (int k4 = 0; k4 < HID / 4; k4++) {
            float w0 = g_Wa1hT[(k4 * 4 + 0) * HID + t];
            float w1 = g_Wa1hT[(k4 * 4 + 1) * HID + t];
            float w2 = g_Wa1hT[(k4 * 4 + 2) * HID + t];
            float w3 = g_Wa1hT[(k4 * 4 + 3) * HID + t];
            #pragma unroll
            for (int m = 0; m < TILE_M; m++) {
                float4 hv = ((float4*)s_h[m])[k4];
                acc[m] += hv.x * w0 + hv.y * w1 + hv.z * w2 + hv.w * w3;
            }
        }
        #pragma unroll
        for (int m = 0; m < TILE_M; m++) s_buf[m][t] = fmaxf(acc[m], 0.f);
    }
    __syncthreads();

    // ---- a2: s_out = a1 @ Wa2.T + (ba2 - bg2) ----
    {
        int j2 = t & 63, half = t >> 6, m0 = half * 8;
        float acc[8];
        float bias = g_bout[j2];
        #pragma unroll
        for (int mi = 0; mi < 8; mi++) acc[mi] = bias;
        #pragma unroll 4
        for (int k4 = 0; k4 < HID / 4; k4++) {
            float w0 = g_Wa2T[(k4 * 4 + 0) * OUT_D + j2];
            float w1 = g_Wa2T[(k4 * 4 + 1) * OUT_D + j2];
            float w2 = g_Wa2T[(k4 * 4 + 2) * OUT_D + j2];
            float w3 = g_Wa2T[(k4 * 4 + 3) * OUT_D + j2];
            #pragma unroll
            for (int mi = 0; mi < 8; mi++) {
                float4 hv = ((float4*)s_buf[m0 + mi])[k4];
                acc[mi] += hv.x * w0 + hv.y * w1 + hv.z * w2 + hv.w * w3;
            }
        }
        #pragma unroll
        for (int mi = 0; mi < 8; mi++) s_out[m0 + mi][j2] = acc[mi];
    }
    __syncthreads();

    // ---- g1 = relu(h @ Wg1h.T + xg1) (overwrite s_buf) ----
    {
        float acc[TILE_M];
        float bias = g_xg1[t];
        #pragma unroll
        for (int m = 0; m < TILE_M; m++) acc[m] = bias;
        #pragma unroll 4
        for (int k4 = 0; k4 < HID / 4; k4++) {
            float w0 = g_Wg1hT[(k4 * 4 + 0) * HID + t];
            float w1 = g_Wg1hT[(k4 * 4 + 1) * HID + t];
            float w2 = g_Wg1hT[(k4 * 4 + 2) * HID + t];
            float w3 = g_Wg1hT[(k4 * 4 + 3) * HID + t];
            #pragma unroll
            for (int m = 0; m < TILE_M; m++) {
                float4 hv = ((float4*)s_h[m])[k4];
                acc[m] += hv.x * w0 + hv.y * w1 + hv.z * w2 + hv.w * w3;
            }
        }
        #pragma unroll
        for (int m = 0; m < TILE_M; m++) s_buf[m][t] = fmaxf(acc[m], 0.f);
    }
    __syncthreads();

    // ---- g2: s_out -= g1 @ Wg2.T  (out = a - g) ----
    {
        int j2 = t & 63, half = t >> 6, m0 = half * 8;
        float acc[8];
        #pragma unroll
        for (int mi = 0; mi < 8; mi++) acc[mi] = 0.f;
        #pragma unroll 4
        for (int k4 = 0; k4 < HID / 4; k4++) {
            float w0 = g_Wg2T[(k4 * 4 + 0) * OUT_D + j2];
            float w1 = g_Wg2T[(k4 * 4 + 1) * OUT_D + j2];
            float w2 = g_Wg2T[(k4 * 4 + 2) * OUT_D + j2];
            float w3 = g_Wg2T[(k4 * 4 + 3) * OUT_D + j2];
            #pragma unroll
            for (int mi = 0; mi < 8; mi++) {
                float4 hv = ((float4*)s_buf[m0 + mi])[k4];
                acc[mi] += hv.x * w0 + hv.y * w1 + hv.z * w2 + hv.w * w3;
            }
        }
        #pragma unroll
        for (int mi = 0; mi < 8; mi++) s_out[m0 + mi][j2] -= acc[mi];
    }
    __syncthreads();

    // ---- tension[m] = mean(out[m]^2); e[m] = exp(t[m]) ----
    {
        int m = t >> 3, p = t & 7;
        float s = 0.f;
        #pragma unroll
        for (int c = 0; c < 8; c++) {
            float v = s_out[m][p * 8 + c];
            s += v * v;
        }
        s += __shfl_down_sync(0xffffffffu, s, 4, 8);
        s += __shfl_down_sync(0xffffffffu, s, 2, 8);
        s += __shfl_down_sync(0xffffffffu, s, 1, 8);
        if (p == 0) {
            float tv = s * (1.f / OUT_D);
            s_t[m] = tv;
            s_e[m] = expf(tv);
        }
    }
    __syncthreads();

    // ---- fused GRU: r/z/n in one sweep over (out, tension, h) ----
    {
        float accR[TILE_M], accZ[TILE_M], accNh[TILE_M], accNi[TILE_M];
        float br  = b_ih[t]           + b_hh[t];
        float bz  = b_ih[HID + t]     + b_hh[HID + t];
        float bni = b_ih[2 * HID + t];
        float bnh = b_hh[2 * HID + t];
        #pragma unroll
        for (int m = 0; m < TILE_M; m++) {
            accR[m] = br; accZ[m] = bz; accNi[m] = bni; accNh[m] = bnh;
        }
        // out part (K = 64) via W_ih
        #pragma unroll 2
        for (int k4 = 0; k4 < OUT_D / 4; k4++) {
            float wr0 = g_WihT[(k4*4+0)*G3 + t],           wr1 = g_WihT[(k4*4+1)*G3 + t];
            float wr2 = g_WihT[(k4*4+2)*G3 + t],           wr3 = g_WihT[(k4*4+3)*G3 + t];
            float wz0 = g_WihT[(k4*4+0)*G3 + HID + t],     wz1 = g_WihT[(k4*4+1)*G3 + HID + t];
            float wz2 = g_WihT[(k4*4+2)*G3 + HID + t],     wz3 = g_WihT[(k4*4+3)*G3 + HID + t];
            float wn0 = g_WihT[(k4*4+0)*G3 + 2*HID + t],   wn1 = g_WihT[(k4*4+1)*G3 + 2*HID + t];
            float wn2 = g_WihT[(k4*4+2)*G3 + 2*HID + t],   wn3 = g_WihT[(k4*4+3)*G3 + 2*HID + t];
            #pragma unroll
            for (int m = 0; m < TILE_M; m++) {
                float4 ov = ((float4*)s_out[m])[k4];
                accR[m]  += ov.x * wr0 + ov.y * wr1 + ov.z * wr2 + ov.w * wr3;
                accZ[m]  += ov.x * wz0 + ov.y * wz1 + ov.z * wz2 + ov.w * wz3;
                accNi[m] += ov.x * wn0 + ov.y * wn1 + ov.z * wn2 + ov.w * wn3;
            }
        }
        // tension column (k = 64)
        {
            float wr = g_WihT[64 * G3 + t];
            float wz = g_WihT[64 * G3 + HID + t];
            float wn = g_WihT[64 * G3 + 2 * HID + t];
            #pragma unroll
            for (int m = 0; m < TILE_M; m++) {
                float tv = s_t[m];
                accR[m]  += tv * wr;
                accZ[m]  += tv * wz;
                accNi[m] += tv * wn;
            }
        }
        // h part (K = 128) via W_hh
        #pragma unroll 2
        for (int k4 = 0; k4 < HID / 4; k4++) {
            float wr0 = g_WhhT[(k4*4+0)*G3 + t],           wr1 = g_WhhT[(k4*4+1)*G3 + t];
            float wr2 = g_WhhT[(k4*4+2)*G3 + t],           wr3 = g_WhhT[(k4*4+3)*G3 + t];
            float wz0 = g_WhhT[(k4*4+0)*G3 + HID + t],     wz1 = g_WhhT[(k4*4+1)*G3 + HID + t];
            float wz2 = g_WhhT[(k4*4+2)*G3 + HID + t],     wz3 = g_WhhT[(k4*4+3)*G3 + HID + t];
            float wn0 = g_WhhT[(k4*4+0)*G3 + 2*HID + t],   wn1 = g_WhhT[(k4*4+1)*G3 + 2*HID + t];
            float wn2 = g_WhhT[(k4*4+2)*G3 + 2*HID + t],   wn3 = g_WhhT[(k4*4+3)*G3 + 2*HID + t];
            #pragma unroll
            for (int m = 0; m < TILE_M; m++) {
                float4 hv = ((float4*)s_h[m])[k4];
                accR[m]  += hv.x * wr0 + hv.y * wr1 + hv.z * wr2 + hv.w * wr3;
                accZ[m]  += hv.x * wz0 + hv.y * wz1 + hv.z * wz2 + hv.w * wz3;
                accNh[m] += hv.x * wn0 + hv.y * wn1 + hv.z * wn2 + hv.w * wn3;
            }
        }
        float colsum = 0.f;
        #pragma unroll
        for (int m = 0; m < TILE_M; m++) {
            float r  = 1.f / (1.f + expf(-accR[m]));
            float z  = 1.f / (1.f + expf(-accZ[m]));
            float nn = tanhf(accNi[m] + r * accNh[m]);
            float nh = (1.f - z) * nn + z * s_h[m][t];
            g_hpre[(size_t)(base + m) * HID + t] = nh;
            colsum += nh;
        }
        g_partial_fm[(size_t)blockIdx.x * HID + t] = colsum;
    }

    // ---- softmax partials (reads s_e, s_out — stable since last sync) ----
    if (t < OUT_D) {
        float s = 0.f;
        #pragma unroll
        for (int m = 0; m < TILE_M; m++) s += s_e[m] * s_out[m][t];
        g_partial_sm[(size_t)blockIdx.x * 66 + t] = s;
    } else if (t == OUT_D) {
        float s = 0.f;
        #pragma unroll
        for (int m = 0; m < TILE_M; m++) s += s_e[m];
        g_partial_sm[(size_t)blockIdx.x * 66 + 64] = s;
    } else if (t == OUT_D + 1) {
        float s = 0.f;
        #pragma unroll
        for (int m = 0; m < TILE_M; m++) s += s_t[m];
        g_partial_sm[(size_t)blockIdx.x * 66 + 65] = s;
    }
}

// ---------------------------------------------------------------------------
// Stage 4: single-block deterministic reductions
// ---------------------------------------------------------------------------
__global__ void __launch_bounds__(1024)
reduce_kernel(float* __restrict__ out, int n, int n_f, int fs)
{
    const int ncta = n / TILE_M;
    const int cpf  = fs / TILE_M;
    const int t = threadIdx.x;

    // faction means
    for (int i = t; i < n_f * HID; i += blockDim.x) {
        int f = i / HID, c = i % HID;
        float s = 0.f;
        const float* p = &g_partial_fm[(size_t)(f * cpf) * HID + c];
        for (int b = 0; b < cpf; b++) s += p[(size_t)b * HID];
        g_fm[i] = s / (float)fs;
    }
    __syncthreads();

    // global mean (mean of faction means)
    for (int c = t; c < HID; c += blockDim.x) {
        float s = 0.f;
        for (int f = 0; f < n_f; f++) s += g_fm[f * HID + c];
        g_go[c] = s / (float)n_f;
    }

    // softmax + tension reduction: 66 columns, 15 partial lanes each
    __shared__ float s_red[15][66];
    __shared__ float s_tot[66];
    if (t < 15 * 66) {
        int part = t / 66, col = t % 66;
        float s = 0.f;
        for (int b = part; b < ncta; b += 15) s += g_partial_sm[(size_t)b * 66 + col];
        s_red[part][col] = s;
    }
    __syncthreads();
    if (t < 66) {
        float s = 0.f;
        #pragma unroll
        for (int p = 0; p < 15; p++) s += s_red[p][t];
        s_tot[t] = s;
    }
    __syncthreads();
    if (t < OUT_D) {
        out[t] = s_tot[t] / s_tot[64];          // combined = sum(e*out)/sum(e)
    } else if (t == OUT_D) {
        out[OUT_D] = s_tot[65] / (float)n;      // mean_tension
    }
}

// ---------------------------------------------------------------------------
// Stage 5: faction sync/debate mix + scatter into output hidden state
// ---------------------------------------------------------------------------
__global__ void finalize_kernel(float* __restrict__ outH,
                                const int* __restrict__ alive_idx,
                                const int* __restrict__ step_ptr,
                                int n, int n_f, int fs, int dc)
{
    int i = blockIdx.x * blockDim.x + threadIdx.x;
    int total = n * HID;
    if (i >= total) return;
    int r = i >> 7;       // / HID
    int c = i & 127;      // % HID
    float v = g_hpre[i];
    if (n_f >= 2) {
        int f = r / fs;
        v = 0.85f * v + 0.15f * g_fm[f * HID + c];
        int step = *step_ptr;
        if (step > 5 && (r - f * fs) < dc)
            v = 0.85f * v + 0.15f * g_go[c];
    }
    outH[(size_t)alive_idx[r] * HID + c] = v;
}

// ---------------------------------------------------------------------------
extern "C" void kernel_launch(void* const* d_in, const int* in_sizes, int n_in,
                              void* d_out, int out_size)
{
    const float* x       = (const float*)d_in[0];
    const float* hiddens = (const float*)d_in[1];
    const float* Wa1     = (const float*)d_in[2];
    const float* ba1     = (const float*)d_in[3];
    const float* Wa2     = (const float*)d_in[4];
    const float* ba2     = (const float*)d_in[5];
    const float* Wg1     = (const float*)d_in[6];
    const float* bg1     = (const float*)d_in[7];
    const float* Wg2     = (const float*)d_in[8];
    const float* bg2     = (const float*)d_in[9];
    const float* Wih     = (const float*)d_in[10];
    const float* Whh     = (const float*)d_in[11];
    const float* b_ih    = (const float*)d_in[12];
    const float* b_hh    = (const float*)d_in[13];
    const int*   alive   = (const int*)  d_in[14];
    const int*   step    = (const int*)  d_in[15];

    int n = in_sizes[14];                    // n_alive (131072)
    if (n > N_ALIVE_MAX) n = N_ALIVE_MAX;    // scratch guard (never expected)

    float* out  = (float*)d_out;
    float* outH = out + OUT_D + 1;           // new_hiddens region

    // 1) copy full hidden state into output (alive rows overwritten later)
    cudaMemcpyAsync(outH, hiddens, (size_t)in_sizes[1] * sizeof(float),
                    cudaMemcpyDeviceToDevice, 0);

    // 2) weight prep
    setup_kernel<<<96, 256>>>(x, Wa1, ba1, Wa2, ba2, Wg1, bg1, Wg2, bg2, Wih, Whh);

    // 3) main fused compute
    int nblk = n / TILE_M;
    main_kernel<<<nblk, THREADS_B>>>(hiddens, alive, b_ih, b_hh, n);

    // 4) reductions
    int n_f = (n / 2 < 8) ? (n / 2) : 8;
    if (n_f < 1) n_f = 1;
    int fs  = (n_f > 0) ? n / n_f : n;
    int dc  = fs / 4; if (dc < 1) dc = 1;
    reduce_kernel<<<1, 1024>>>(out, n, n_f, fs);

    // 5) faction mix + scatter
    int total = n * HID;
    finalize_kernel<<<(total + 255) / 256, 256>>>(outH, alive, step, n, n_f, fs, dc);
}